// round 12
// baseline (speedup 1.0000x reference)
#include <cuda_runtime.h>
#include <cstdint>
#include <cstddef>

#define L_SEQ 32768
#define DIM   512
#define DIM4  2048
#define NCTA  32          // recurrence CTAs
#define NBLK  256         // row-blocks of 128 rows
#define NTIL  4096        // 256 row-blocks x 16 col-tiles

// Scratch (static device globals: allocation-free per harness rules)
__device__ float g_xp[(size_t)L_SEQ * DIM4];      // 256 MB x-projection
__device__ unsigned long long g_hx[2][DIM];       // tagged hidden: (tag<<32)|bits
__device__ int g_cnt[NBLK];                       // per-row-block completed tiles

__device__ __forceinline__ uint32_t smem_u32(const void* p) {
    uint32_t a;
    asm("{ .reg .u64 t; cvta.to.shared.u64 t, %1; cvt.u32.u64 %0, t; }"
        : "=r"(a) : "l"(p));
    return a;
}

// ---------------------------------------------------------------------------
// Phase 0: reset global state each launch (graph-replay safe)
// ---------------------------------------------------------------------------
__global__ void init_state(const float* __restrict__ h0) {
    int tid = threadIdx.x;
    if (tid < NBLK) g_cnt[tid] = 0;
    if (tid < DIM) {
        g_hx[0][tid] = (unsigned long long)__float_as_uint(h0[tid]);  // tag 0
        g_hx[1][tid] = 0xFFFFFFFF00000000ull;                         // tag ~0
    }
}

struct GemmSmem { float As[16][132]; float Bs[16][128]; };   // 16.6 KB
struct RecSmem  {
    unsigned long long hloc[2][256];   // DSMEM-delivered tagged local h
    float hsh[2][DIM];
    float xpsh[2][64];
};

// ---------------------------------------------------------------------------
// Fused kernel, templated on cluster size CLS (8 or 16) and GEMM CTA count.
// CTAs 0..31: sequential LSTM. Intra-cluster h half (CLS*16 values) travels
// via DSMEM fire-and-forget stores (poll = LDS); the rest via tagged L2
// words. CTAs 32..32+GC-1: persistent x-projection GEMM.
// ---------------------------------------------------------------------------
template<int CLS, int GC>
__global__ __launch_bounds__(512, 1) void lstm_fused(
    const float* __restrict__ xs, const float* __restrict__ Wi,
    const float* __restrict__ bias, const float* __restrict__ Wh,
    const float* __restrict__ c0, const float* __restrict__ h0,
    float* __restrict__ out)
{
    constexpr int LOCALN = CLS * 16;    // local h values per cluster
    constexpr int PHA    = CLS / 4;     // phase-A m-groups (local)
    __shared__ __align__(16) unsigned char s_raw[sizeof(GemmSmem) > sizeof(RecSmem)
                                                 ? sizeof(GemmSmem) : sizeof(RecSmem)];
    const int tid = threadIdx.x;
    const int blk = blockIdx.x;

    // =================== GEMM path ===================
    if (blk >= NCTA) {
        GemmSmem& S = *reinterpret_cast<GemmSmem*>(s_raw);
        const int tx = tid & 31;
        const int ty = tid >> 5;

        for (int idx = blk - NCTA; idx < NTIL; idx += GC) {
            const int bm = (idx >> 4) * 128;   // row-major tile order
            const int bn = (idx & 15) * 128;

            float acc[8][4];
#pragma unroll
            for (int i = 0; i < 8; i++)
#pragma unroll
                for (int j = 0; j < 4; j++) acc[i][j] = 0.f;

            for (int k0 = 0; k0 < DIM; k0 += 16) {
                {   // A tile 128x16, transposed into As[k][m]
                    int row = tid >> 2;
                    int c4  = (tid & 3) << 2;
                    float4 v = *(const float4*)(xs + (size_t)(bm + row) * DIM + k0 + c4);
                    S.As[c4 + 0][row] = v.x;
                    S.As[c4 + 1][row] = v.y;
                    S.As[c4 + 2][row] = v.z;
                    S.As[c4 + 3][row] = v.w;
                }
                {   // B tile 16x128
                    int row = tid >> 5;
                    int c4  = (tid & 31) << 2;
                    *(float4*)(&S.Bs[row][c4]) =
                        *(const float4*)(Wi + (size_t)(k0 + row) * DIM4 + bn + c4);
                }
                __syncthreads();
#pragma unroll
                for (int kk = 0; kk < 16; kk++) {
                    float a[8], bb[4];
                    *(float4*)(a)     = *(const float4*)(&S.As[kk][ty * 8]);
                    *(float4*)(a + 4) = *(const float4*)(&S.As[kk][ty * 8 + 4]);
                    *(float4*)(bb)    = *(const float4*)(&S.Bs[kk][tx * 4]);
#pragma unroll
                    for (int i = 0; i < 8; i++)
#pragma unroll
                        for (int j = 0; j < 4; j++)
                            acc[i][j] = fmaf(a[i], bb[j], acc[i][j]);
                }
                __syncthreads();
            }

            float4 bv = *(const float4*)(bias + bn + tx * 4);
#pragma unroll
            for (int i = 0; i < 8; i++) {
                float4 o;
                o.x = acc[i][0] + bv.x;
                o.y = acc[i][1] + bv.y;
                o.z = acc[i][2] + bv.z;
                o.w = acc[i][3] + bv.w;
                *(float4*)(g_xp + (size_t)(bm + ty * 8 + i) * DIM4 + bn + tx * 4) = o;
            }
            __threadfence();
            __syncthreads();
            if (tid == 0) atomicAdd(&g_cnt[idx >> 4], 1);
        }
        return;
    }

    // =================== Recurrence path (CTAs 0..31) ===================
    RecSmem& R = *reinterpret_cast<RecSmem*>(s_raw);
    const int w  = tid >> 5;               // warp 0..15 -> local d
    const int l  = tid & 31;
    const int d  = blk * 16 + w;
    const int g  = l >> 3;                 // lane-group -> gate (0:i 1:f 2:g 3:o)
    const int cb = (blk / CLS) * LOCALN;   // this cluster's k/d base
    const int ls = (blk % CLS) * 16 + w;   // own slot in cluster-local hloc

    // Register-resident weights, k rotated so m < PHA is the LOCAL part:
    // lane l covers k = (cb + 2l + 64m + j) mod 512
    float wreg[4][8][2];
#pragma unroll
    for (int q = 0; q < 4; q++)
#pragma unroll
        for (int m = 0; m < 8; m++) {
            int kb = (cb + 2 * l + 64 * m) & 511;
#pragma unroll
            for (int j = 0; j < 2; j++)
                wreg[q][m][j] = __ldg(Wh + (size_t)(kb + j) * DIM4 + q * DIM + d);
        }

    float cst = __ldg(c0 + d);

    const float escale = (g == 2) ? -2.0f : -1.0f;
    const float pa     = (g == 2) ?  2.0f :  1.0f;
    const float pb     = (g == 2) ? -1.0f :  0.0f;

    const float* xp_base = g_xp + (tid >> 4) * DIM + blk * 16 + (tid & 15);
    const unsigned FULL = 0xffffffffu;

    // Init local tagged buffer: buf0 <- {tag0, h0}, buf1 <- never-match
    if (tid < LOCALN) {
        R.hloc[0][tid] = (unsigned long long)__float_as_uint(__ldg(h0 + cb + tid));
        R.hloc[1][tid] = 0xFFFFFFFF00000000ull;
    }
    __syncthreads();
    // Peers' hloc must be initialized before anyone's step-0 publish
    asm volatile("barrier.cluster.arrive.aligned;" ::: "memory");
    asm volatile("barrier.cluster.wait.aligned;"   ::: "memory");

    int rdy = 0;   // row-blocks confirmed complete (tid0 only)
    if (tid == 0) {
        while (rdy < 1) {
            int c;
            asm volatile("ld.acquire.gpu.global.b32 %0, [%1];"
                         : "=r"(c) : "l"(g_cnt + rdy));
            if (c == 16) rdy++;
        }
    }
    __syncthreads();

    float xv = (tid < 64) ? __ldcs(xp_base) : 0.f;

#define DO_MM(mm)                                                              \
    do {                                                                       \
        float2 hv = *(const float2*)(&R.hsh[pbuf][(cb + 2 * l + 64 * (mm)) & 511]); \
        s0 = fmaf(hv.x, wreg[0][mm][0], fmaf(hv.y, wreg[0][mm][1], s0));       \
        s1 = fmaf(hv.x, wreg[1][mm][0], fmaf(hv.y, wreg[1][mm][1], s1));       \
        s2 = fmaf(hv.x, wreg[2][mm][0], fmaf(hv.y, wreg[2][mm][1], s2));       \
        s3 = fmaf(hv.x, wreg[3][mm][0], fmaf(hv.y, wreg[3][mm][1], s3));       \
    } while (0)

    for (int t = 0; t < L_SEQ; t++) {
        const int pbuf = t & 1;
        const unsigned want = (unsigned)t;
        float s0 = 0.f, s1 = 0.f, s2 = 0.f, s3 = 0.f;

        if (tid < LOCALN) {
            // ---- local warps: local h via DSMEM-written smem ----
            if (tid < 64) R.xpsh[pbuf][tid] = xv;
            {
                uint32_t pa_ = smem_u32(&R.hloc[pbuf][tid]);
                unsigned long long v;
                do {
                    asm volatile("ld.relaxed.cluster.shared.b64 %0, [%1];"
                                 : "=l"(v) : "r"(pa_));
                } while ((unsigned)(v >> 32) != want);
                R.hsh[pbuf][cb + tid] = __uint_as_float((unsigned)v);
            }
            if (tid == 0) {   // GEMM row-block readiness for prefetch t+1
                int need = ((t + 1) >> 7) + 1;
                if (need > NBLK) need = NBLK;
                while (rdy < need) {
                    int c;
                    asm volatile("ld.acquire.gpu.global.b32 %0, [%1];"
                                 : "=r"(c) : "l"(g_cnt + rdy));
                    if (c == 16) rdy++;
                }
            }
            asm volatile("bar.sync 1, %0;" :: "n"(LOCALN) : "memory");
            if (tid < 64 && t + 1 < L_SEQ)
                xv = __ldcs(xp_base + (size_t)(t + 1) * DIM4);
            // Phase A (local m-groups) overlaps the remote L2 flight
#pragma unroll
            for (int m = 0; m < PHA; m++) DO_MM(m);
            asm volatile("bar.sync 2, 512;" ::: "memory");
        } else {
            // ---- remote warps: tagged L2 words, phase-staggered dual chain ----
            const int rk = (cb + tid) & 511;
            const unsigned long long* hp = &g_hx[pbuf][rk];
            unsigned long long va, vb, v;
            asm volatile("ld.relaxed.gpu.global.b64 %0, [%1];"
                         : "=l"(va) : "l"(hp));
            unsigned dly = tid | 1u;          // ~220cy opaque phase offset
#pragma unroll
            for (int i = 0; i < 48; i++)
                asm volatile("mad.lo.u32 %0, %0, 3, 1;" : "+r"(dly));
            unsigned zr = __shfl_sync(FULL, dly, l) ^ dly;   // == 0, opaque
            const unsigned long long* hpb =
                (const unsigned long long*)((const char*)hp + zr);
            asm volatile("ld.relaxed.gpu.global.b64 %0, [%1];"
                         : "=l"(vb) : "l"(hpb));
            for (;;) {
                if ((unsigned)(va >> 32) == want) { v = va; break; }
                asm volatile("ld.relaxed.gpu.global.b64 %0, [%1];"
                             : "=l"(va) : "l"(hp));
                if ((unsigned)(vb >> 32) == want) { v = vb; break; }
                asm volatile("ld.relaxed.gpu.global.b64 %0, [%1];"
                             : "=l"(vb) : "l"(hpb));
            }
            R.hsh[pbuf][rk] = __uint_as_float((unsigned)v);
            asm volatile("bar.sync 2, 512;" ::: "memory");
#pragma unroll
            for (int m = 0; m < PHA; m++) DO_MM(m);
        }

        // Phase B: remote m-groups (hsh complete after bar 2)
#pragma unroll
        for (int m = PHA; m < 8; m++) DO_MM(m);

        // Merged butterfly reduce: 4 sums over 32 lanes, ~9 shfls;
        // lane-group g ends holding gate-g total.
        float t0 = __shfl_xor_sync(FULL, s0, 16);
        float t2 = __shfl_xor_sync(FULL, s2, 16);
        float av = (l < 16) ? (s0 + t0) : (s2 + t2);
        float t1 = __shfl_xor_sync(FULL, s1, 16);
        float t3 = __shfl_xor_sync(FULL, s3, 16);
        float bv = (l < 16) ? (s1 + t1) : (s3 + t3);
        float a8 = __shfl_xor_sync(FULL, av, 8);
        float b8 = __shfl_xor_sync(FULL, bv, 8);
        float cc = ((l & 8) == 0) ? (av + a8) : (bv + b8);
        cc += __shfl_xor_sync(FULL, cc, 4);
        cc += __shfl_xor_sync(FULL, cc, 2);
        cc += __shfl_xor_sync(FULL, cc, 1);

        // Activation (branchless per lane-group)
        float y   = cc + R.xpsh[pbuf][g * 16 + w];
        float e   = __expf(escale * y);
        float r   = __fdividef(1.0f, 1.0f + e);
        float act = fmaf(pa, r, pb);   // sigmoid(y) or tanh(y)

        float vi = __shfl_sync(FULL, act, 0);
        float vf = __shfl_sync(FULL, act, 8);
        float vg = __shfl_sync(FULL, act, 16);
        float vo = __shfl_sync(FULL, act, 24);

        cst = fmaf(vf, cst, vi * vg);
        float ca = fminf(fmaxf(cst, -40.f), 40.f);
        float e2 = __expf(-2.0f * ca);
        float th = fmaf(2.0f, __fdividef(1.0f, 1.0f + e2), -1.0f);
        float hn = vo * th;

        if (l == 0) {
            unsigned long long pk =
                ((unsigned long long)(unsigned)(t + 1) << 32) |
                (unsigned long long)__float_as_uint(hn);
            // L2 word first (longest flight), then CLS DSMEM peer copies
            asm volatile("st.relaxed.gpu.global.b64 [%0], %1;"
                         :: "l"(&g_hx[(t + 1) & 1][d]), "l"(pk) : "memory");
            uint32_t laddr = smem_u32(&R.hloc[(t + 1) & 1][ls]);
#pragma unroll
            for (int rr = 0; rr < CLS; rr++) {
                uint32_t rem;
                asm("mapa.shared::cluster.u32 %0, %1, %2;"
                    : "=r"(rem) : "r"(laddr), "r"(rr));
                asm volatile("st.relaxed.cluster.shared::cluster.b64 [%0], %1;"
                             :: "r"(rem), "l"(pk) : "memory");
            }
        } else if (l == 1) {
            __stcs(out + (size_t)t * DIM + d, hn);
        }
        // no trailing barrier: hloc/hsh/xpsh all double-buffered
    }
#undef DO_MM
}

// ---------------------------------------------------------------------------
extern "C" void kernel_launch(void* const* d_in, const int* in_sizes, int n_in,
                              void* d_out, int out_size)
{
    const float* xs = (const float*)d_in[0];   // [L, 512]
    const float* Wi = (const float*)d_in[1];   // [512, 2048]
    const float* Wh = (const float*)d_in[2];   // [512, 2048]
    const float* b  = (const float*)d_in[3];   // [2048]
    const float* c0 = (const float*)d_in[4];   // [512]
    const float* h0 = (const float*)d_in[5];   // [512]
    float* out = (float*)d_out;                // [L, 512]

    init_state<<<1, 512>>>(h0);

    // Preferred: 16-CTA non-portable clusters (grid 112 = 7 clusters).
    cudaFuncSetAttribute((const void*)lstm_fused<16, 80>,
                         cudaFuncAttributeNonPortableClusterSizeAllowed, 1);

    cudaLaunchConfig_t cfg16 = {};
    cfg16.gridDim  = dim3(NCTA + 80, 1, 1);
    cfg16.blockDim = dim3(512, 1, 1);
    cudaLaunchAttribute a16[1];
    a16[0].id = cudaLaunchAttributeClusterDimension;
    a16[0].val.clusterDim.x = 16;
    a16[0].val.clusterDim.y = 1;
    a16[0].val.clusterDim.z = 1;
    cfg16.attrs = a16;
    cfg16.numAttrs = 1;

    int maxC = 0;
    cudaError_t qe = cudaOccupancyMaxActiveClusters(&maxC, lstm_fused<16, 80>, &cfg16);

    if (qe == cudaSuccess && maxC >= 7) {
        cudaLaunchKernelEx(&cfg16, lstm_fused<16, 80>, xs, Wi, b, Wh, c0, h0, out);
    } else {
        // Proven fallback: 8-CTA clusters, grid 128
        cudaLaunchConfig_t cfg8 = {};
        cfg8.gridDim  = dim3(NCTA + 96, 1, 1);
        cfg8.blockDim = dim3(512, 1, 1);
        cudaLaunchAttribute a8[1];
        a8[0].id = cudaLaunchAttributeClusterDimension;
        a8[0].val.clusterDim.x = 8;
        a8[0].val.clusterDim.y = 1;
        a8[0].val.clusterDim.z = 1;
        cfg8.attrs = a8;
        cfg8.numAttrs = 1;
        cudaLaunchKernelEx(&cfg8, lstm_fused<8, 96>, xs, Wi, b, Wh, c0, h0, out);
    }
}